// round 3
// baseline (speedup 1.0000x reference)
#include <cuda_runtime.h>
#include <cuda_bf16.h>

#define NP   4096
#define KNN  32
#define CIN  16
#define COUT 32
#define NB   27      // 3*3*3 basis terms
#define NG   432     // CIN*NB

__device__ float4 g_posq[NP];
__device__ float  g_cscratch[NP * 3];
__device__ float  g_oscratch[NP * COUT];

// ---------------------------------------------------------------------------
// LAPACK fp32 helpers (conventions of LAPACK >= 3.10, as bundled w/ scipy)
// ---------------------------------------------------------------------------
__device__ __forceinline__ float slapy2f(float x, float y) {
    float xa = fabsf(x), ya = fabsf(y);
    float w = fmaxf(xa, ya), z = fminf(xa, ya);
    if (z == 0.f) return w;
    float t = z / w;
    return w * sqrtf(1.f + t * t);
}

__device__ __forceinline__ void slartgf(float f, float g, float* c, float* s, float* r) {
    if (g == 0.f)      { *c = 1.f; *s = 0.f; *r = f; }
    else if (f == 0.f) { *c = 0.f; *s = (g > 0.f) ? 1.f : -1.f; *r = fabsf(g); }
    else {
        float d = sqrtf(f * f + g * g);
        float p = 1.f / d;
        *c = fabsf(f) * p;
        *s = g * copysignf(p, f);
        *r = copysignf(d, f);
    }
}

__device__ void slaev2f(float a, float b, float c, float* rt1, float* rt2,
                        float* cs1, float* sn1) {
    float sm = a + c, df = a - c;
    float adf = fabsf(df);
    float tb = b + b, ab = fabsf(tb);
    float acmx, acmn;
    if (fabsf(a) > fabsf(c)) { acmx = a; acmn = c; } else { acmx = c; acmn = a; }
    float rt;
    if (adf > ab)      { float t = ab / adf; rt = adf * sqrtf(1.f + t * t); }
    else if (adf < ab) { float t = adf / ab; rt = ab * sqrtf(1.f + t * t); }
    else               rt = ab * sqrtf(2.f);
    int sgn1;
    if (sm < 0.f)      { *rt1 = 0.5f * (sm - rt); sgn1 = -1;
                         *rt2 = (acmx / *rt1) * acmn - (b / *rt1) * b; }
    else if (sm > 0.f) { *rt1 = 0.5f * (sm + rt); sgn1 = 1;
                         *rt2 = (acmx / *rt1) * acmn - (b / *rt1) * b; }
    else               { *rt1 = 0.5f * rt; *rt2 = -0.5f * rt; sgn1 = 1; }
    float cs; int sgn2;
    if (df >= 0.f) { cs = df + rt; sgn2 = 1; } else { cs = df - rt; sgn2 = -1; }
    float acs = fabsf(cs);
    if (acs > ab) {
        float ct = -tb / cs;
        *sn1 = 1.f / sqrtf(1.f + ct * ct);
        *cs1 = ct * *sn1;
    } else {
        if (ab == 0.f) { *cs1 = 1.f; *sn1 = 0.f; }
        else {
            float tn = -cs / tb;
            *cs1 = 1.f / sqrtf(1.f + tn * tn);
            *sn1 = tn * *cs1;
        }
    }
    if (sgn1 == sgn2) { float tn = *cs1; *cs1 = -*sn1; *sn1 = tn; }
}

// ssteqr('I', n=3). D/E in, eigvecs accumulated into z (init to I inside).
// 1-based internal indexing to mirror netlib exactly.
__device__ void ssteqr3(float* D, float* E, float z[3][3]) {
    const float eps = 5.9604645e-08f, eps2 = eps * eps, safmin = 1.17549435e-38f;
    const int n = 3, nmaxit = 90;
    float d[4] = {0.f, D[0], D[1], D[2]};
    float e[3] = {0.f, E[0], E[1]};
    for (int i = 0; i < 3; ++i)
        for (int j = 0; j < 3; ++j) z[i][j] = (i == j) ? 1.f : 0.f;
    int jtot = 0, l1 = 1;
    float wc[3], ws[3];

    while (l1 <= n) {
        if (l1 > 1) e[l1 - 1] = 0.f;
        int m = n;
        for (int mm = l1; mm <= n - 1; ++mm) {
            float tst = fabsf(e[mm]);
            if (tst == 0.f) { m = mm; break; }
            if (tst <= (sqrtf(fabsf(d[mm])) * sqrtf(fabsf(d[mm + 1]))) * eps) {
                e[mm] = 0.f; m = mm; break;
            }
        }
        int l = m == l1 ? l1 : l1;      // l = l1
        l = l1;
        int lsv = l, lend = m, lendsv = lend;
        l1 = m + 1;
        if (lend == l) continue;
        if (fabsf(d[lend]) < fabsf(d[l])) { lend = lsv; l = lendsv; }

        if (lend > l) {
            // ---- QL ----
            for (;;) {
                int mq = lend;
                if (l != lend) {
                    for (int mi = l; mi <= lend - 1; ++mi) {
                        float tst = e[mi] * e[mi];
                        if (tst <= (eps2 * fabsf(d[mi])) * fabsf(d[mi + 1]) + safmin) {
                            mq = mi; break;
                        }
                    }
                }
                if (mq < lend) e[mq] = 0.f;
                float p = d[l];
                if (mq == l) { d[l] = p; if (++l <= lend) continue; break; }
                if (mq == l + 1) {
                    float rt1, rt2, c, s;
                    slaev2f(d[l], e[l], d[l + 1], &rt1, &rt2, &c, &s);
                    for (int i = 0; i < 3; ++i) {
                        float t = z[i][l];                      // col l+1 (1b) = l (0b)
                        z[i][l]     = c * t - s * z[i][l - 1];
                        z[i][l - 1] = s * t + c * z[i][l - 1];
                    }
                    d[l] = rt1; d[l + 1] = rt2; e[l] = 0.f;
                    l += 2;
                    if (l <= lend) continue;
                    break;
                }
                if (jtot == nmaxit) break;
                ++jtot;
                float g = (d[l + 1] - p) / (2.f * e[l]);
                float r = slapy2f(g, 1.f);
                g = d[mq] - p + (e[l] / (g + copysignf(r, g)));
                float s = 1.f, c = 1.f; p = 0.f;
                for (int i = mq - 1; i >= l; --i) {
                    float f = s * e[i], b = c * e[i];
                    slartgf(g, f, &c, &s, &r);
                    if (i != mq - 1) e[i + 1] = r;
                    g = d[i + 1] - p;
                    r = (d[i] - g) * s + 2.f * c * b;
                    p = s * r;
                    d[i + 1] = g + p;
                    g = c * r - b;
                    wc[i] = c; ws[i] = -s;
                }
                for (int j = mq - l; j >= 1; --j) {             // slasr 'B'
                    float ct = wc[l + j - 1], st = ws[l + j - 1];
                    for (int i = 0; i < 3; ++i) {
                        float t = z[i][l + j - 1];
                        z[i][l + j - 1] = ct * t - st * z[i][l + j - 2];
                        z[i][l + j - 2] = st * t + ct * z[i][l + j - 2];
                    }
                }
                d[l] -= p;
                e[l] = g;
            }
        } else {
            // ---- QR ----
            for (;;) {
                int mq = lend;
                if (l != lend) {
                    for (int mi = l; mi >= lend + 1; --mi) {
                        float tst = e[mi - 1] * e[mi - 1];
                        if (tst <= (eps2 * fabsf(d[mi])) * fabsf(d[mi - 1]) + safmin) {
                            mq = mi; break;
                        }
                    }
                }
                if (mq > lend) e[mq - 1] = 0.f;
                float p = d[l];
                if (mq == l) { d[l] = p; if (--l >= lend) continue; break; }
                if (mq == l - 1) {
                    float rt1, rt2, c, s;
                    slaev2f(d[l - 1], e[l - 1], d[l], &rt1, &rt2, &c, &s);
                    for (int i = 0; i < 3; ++i) {               // slasr 'F', cols l-1,l (1b)
                        float t = z[i][l - 1];
                        z[i][l - 1] = c * t - s * z[i][l - 2];
                        z[i][l - 2] = s * t + c * z[i][l - 2];
                    }
                    d[l - 1] = rt1; d[l] = rt2; e[l - 1] = 0.f;
                    l -= 2;
                    if (l >= lend) continue;
                    break;
                }
                if (jtot == nmaxit) break;
                ++jtot;
                float g = (d[l - 1] - p) / (2.f * e[l - 1]);
                float r = slapy2f(g, 1.f);
                g = d[mq] - p + (e[l - 1] / (g + copysignf(r, g)));
                float s = 1.f, c = 1.f; p = 0.f;
                for (int i = mq; i <= l - 1; ++i) {
                    float f = s * e[i], b = c * e[i];
                    slartgf(g, f, &c, &s, &r);
                    if (i != mq) e[i - 1] = r;
                    g = d[i] - p;
                    r = (d[i + 1] - g) * s + 2.f * c * b;
                    p = s * r;
                    d[i] = g + p;
                    g = c * r - b;
                    wc[i] = c; ws[i] = s;
                }
                for (int j = 1; j <= l - mq; ++j) {             // slasr 'F'
                    float ct = wc[mq + j - 1], st = ws[mq + j - 1];
                    for (int i = 0; i < 3; ++i) {
                        float t = z[i][mq + j - 1];
                        z[i][mq + j - 1] = ct * t - st * z[i][mq + j - 2];
                        z[i][mq + j - 2] = st * t + ct * z[i][mq + j - 2];
                    }
                }
                d[l] -= p;
                e[l - 1] = g;
            }
        }
    }
    // selection sort ascending (netlib label 160), swap eigvec columns
    for (int ii = 2; ii <= n; ++ii) {
        int i = ii - 1, k = i;
        float p = d[i];
        for (int j = ii; j <= n; ++j) if (d[j] < p) { k = j; p = d[j]; }
        if (k != i) {
            d[k] = d[i]; d[i] = p;
            for (int r2 = 0; r2 < 3; ++r2) {
                float t = z[r2][i - 1]; z[r2][i - 1] = z[r2][k - 1]; z[r2][k - 1] = t;
            }
        }
    }
}

// Full eigh path for symmetric 3x3 (ssytd2 'L' + ssteqr + sormtr), fp32,
// BLAS-faithful operation ordering so sign branches match LAPACK.
__device__ void eigh3(const float A[6], float V[3][3]) {
    // A packed lower: a00,a10,a20,a11,a21,a22
    float a00 = A[0], a10 = A[1], a20 = A[2], a11 = A[3], a21 = A[4], a22 = A[5];
    float tau = 0.f, v2 = 0.f, e0, e1, d1 = a11, d2v = a22;
    float xnorm = fabsf(a20);
    if (xnorm == 0.f) { tau = 0.f; e0 = a10; e1 = a21; }
    else {
        float alpha = a10;
        float beta = -copysignf(slapy2f(alpha, xnorm), alpha);
        tau = (beta - alpha) / beta;
        v2 = a20 * (1.f / (alpha - beta));
        e0 = beta;
        // ssymv order: w0 = tau*a11 + tau*(a21*v2); w1 = tau*a21 + (tau*v2)*a22
        float w0 = tau * a11 + tau * (a21 * v2);
        float w1 = tau * a21 + (tau * v2) * a22;
        float aw = -0.5f * tau * (w0 + w1 * v2);
        w0 += aw; w1 += aw * v2;
        // ssyr2 order
        d1  = (a11 - w0) - w0;
        e1  = (a21 - v2 * w0) - w1;
        d2v = (a22 - v2 * w1) - w1 * v2;
    }
    float d[3] = {a00, d1, d2v};
    float e[2] = {e0, e1};
    ssteqr3(d, e, V);
    // sormtr: apply H1 = I - tau v v^T (v=[1,v2]) to rows 1,2
    if (tau != 0.f) {
        for (int j = 0; j < 3; ++j) {
            float s = V[1][j] + v2 * V[2][j];
            V[1][j] -= tau * s;
            V[2][j] -= tau * v2 * s;
        }
    }
}

// ---------------------------------------------------------------------------
__global__ void prep_kernel(const float* __restrict__ pos) {
    int p = blockIdx.x * blockDim.x + threadIdx.x;
    if (p < NP) {
        float x = pos[3 * p], y = pos[3 * p + 1], z = pos[3 * p + 2];
        g_posq[p] = make_float4(x, y, z, x * x + y * y + z * z);
    }
}

__global__ __launch_bounds__(256)
void dcconv_kernel(const float* __restrict__ chan,
                   const float* __restrict__ coef,
                   float* __restrict__ centers_out,
                   float* __restrict__ out) {
    const int p = blockIdx.x;
    const int tid = threadIdx.x;

    __shared__ int                s_nbr[KNN];
    __shared__ float4             s_npos[KNN];
    __shared__ float              s_l[3][KNN];
    __shared__ float              s_center[3];
    __shared__ float              s_ev[3][3];
    __shared__ float              s_basis[KNN][NB];
    __shared__ float              s_feat[KNN][CIN];
    __shared__ float              s_G[NG];
    __shared__ unsigned long long s_wmin[8];
    __shared__ unsigned long long s_winner;

    // ---------- Phase 1: brute kNN, top-32 ascending d2 (tie -> low index) ----
    const float4 pq = g_posq[p];
    unsigned long long keys[16];
#pragma unroll
    for (int j = 0; j < 16; ++j) {
        int cand = tid + (j << 8);
        float4 cq = g_posq[cand];
        float dot = pq.x * cq.x + pq.y * cq.y + pq.z * cq.z;
        float d2 = (pq.w + cq.w) - 2.f * dot;
        unsigned u = __float_as_uint(d2);
        u = (u & 0x80000000u) ? ~u : (u | 0x80000000u);
        keys[j] = ((unsigned long long)u << 32) | (unsigned)cand;
    }
    unsigned long long lmin = keys[0];
#pragma unroll
    for (int j = 1; j < 16; ++j) if (keys[j] < lmin) lmin = keys[j];

    for (int r = 0; r < KNN; ++r) {
        unsigned long long v = lmin;
#pragma unroll
        for (int off = 16; off; off >>= 1) {
            unsigned long long o = __shfl_down_sync(0xffffffffu, v, off);
            if (o < v) v = o;
        }
        if ((tid & 31) == 0) s_wmin[tid >> 5] = v;
        __syncthreads();
        if (tid == 0) {
            unsigned long long w = s_wmin[0];
#pragma unroll
            for (int i = 1; i < 8; ++i) if (s_wmin[i] < w) w = s_wmin[i];
            s_winner = w;
            s_nbr[r] = (int)(w & 0xffffffffu);
        }
        __syncthreads();
        unsigned long long w = s_winner;
        if (lmin == w) {
#pragma unroll
            for (int j = 0; j < 16; ++j) if (keys[j] == w) keys[j] = ~0ULL;
            lmin = keys[0];
#pragma unroll
            for (int j = 1; j < 16; ++j) if (keys[j] < lmin) lmin = keys[j];
        }
    }

    // ---------- Phase 2: center, local coords, covariance, eigh -------------
    if (tid < KNN) s_npos[tid] = g_posq[s_nbr[tid]];
    __syncthreads();
    if (tid == 0) {
        float cx = 0.f, cy = 0.f, cz = 0.f;
        for (int k = 0; k < KNN; ++k) { cx += s_npos[k].x; cy += s_npos[k].y; cz += s_npos[k].z; }
        cx /= (float)KNN; cy /= (float)KNN; cz /= (float)KNN;
        s_center[0] = cx; s_center[1] = cy; s_center[2] = cz;
        centers_out[3 * p]     = cx;
        centers_out[3 * p + 1] = cy;
        centers_out[3 * p + 2] = cz;
    }
    __syncthreads();
    if (tid < KNN) {
        s_l[0][tid] = s_npos[tid].x - s_center[0];
        s_l[1][tid] = s_npos[tid].y - s_center[1];
        s_l[2][tid] = s_npos[tid].z - s_center[2];
    }
    __syncthreads();
    if (tid == 0) {
        float A[6]; int idx = 0;
        for (int d = 0; d < 3; ++d)
            for (int e2 = d; e2 < 3; ++e2) {
                float s = 0.f;
                for (int k = 0; k < KNN; ++k) s += s_l[d][k] * s_l[e2][k];
                A[idx++] = s / (float)KNN;
            }
        // A layout from loop: a00,a01,a02,a11,a12,a22 (== packed lower by symmetry)
        float V[3][3];
        eigh3(A, V);
        for (int i = 0; i < 3; ++i)
            for (int j = 0; j < 3; ++j) s_ev[i][j] = V[i][j];
    }
    __syncthreads();

    // ---------- Phase 3: rotate, spherical coords, basis --------------------
    if (tid < KNN) {
        float lx = s_l[0][tid], ly = s_l[1][tid], lz = s_l[2][tid];
        float x = lx * s_ev[0][0] + ly * s_ev[1][0] + lz * s_ev[2][0];
        float y = lx * s_ev[0][1] + ly * s_ev[1][1] + lz * s_ev[2][1];
        float z = lx * s_ev[0][2] + ly * s_ev[1][2] + lz * s_ev[2][2];
        float r = sqrtf(x * x + y * y + z * z);
        float ct = z / (r + 1e-8f);
        ct = fminf(fmaxf(ct, -1.f + 1e-6f), 1.f - 1e-6f);
        float theta = acosf(ct);
        float phi = atan2f(y, x);
        float rb[3] = {1.f, r, r * r};
        float tb[3] = {1.f, cosf(theta), cosf(2.f * theta)};
        float pb[3] = {1.f, cosf(phi), cosf(2.f * phi)};
#pragma unroll
        for (int n = 0; n < 3; ++n)
#pragma unroll
            for (int l = 0; l < 3; ++l)
#pragma unroll
                for (int m = 0; m < 3; ++m)
                    s_basis[tid][n * 9 + l * 3 + m] = (rb[n] * tb[l]) * pb[m];
    }
    // gather features: 512 loads by 256 threads
    {
        int k = tid >> 4, c = tid & 15;
        s_feat[k][c]      = chan[s_nbr[k] * CIN + c];
        s_feat[k + 16][c] = chan[s_nbr[k + 16] * CIN + c];
    }
    __syncthreads();

    // ---------- Phase 4: G[c*27+nlm] = sum_k basis[k][nlm]*feat[k][c] -------
    for (int j = tid; j < NG; j += 256) {
        int c = j / NB, nlm = j - c * NB;
        float s = 0.f;
#pragma unroll
        for (int k = 0; k < KNN; ++k) s += s_basis[k][nlm] * s_feat[k][c];
        s_G[j] = s;
    }
    __syncthreads();

    // ---------- Phase 5: out[o] = sum_j coef[o*432+j] * G[j] ----------------
    {
        int o = tid >> 3, part = tid & 7;
        const float* cf = coef + o * NG;
        float s = 0.f;
        for (int j = part; j < NG; j += 8) s += cf[j] * s_G[j];
#pragma unroll
        for (int off = 4; off; off >>= 1)
            s += __shfl_down_sync(0xffffffffu, s, off);
        if (part == 0) out[p * COUT + o] = s;
    }
}

extern "C" void kernel_launch(void* const* d_in, const int* in_sizes, int n_in,
                              void* d_out, int out_size) {
    const float* pos  = (const float*)d_in[0];
    const float* chan = (const float*)d_in[1];
    const float* coef = (const float*)d_in[3];

    float* centers_ptr;
    float* out_ptr;
    float* d_outf = (float*)d_out;
    if (out_size == NP * 3 + NP * COUT) {        // (centers, output) concatenated
        centers_ptr = d_outf;
        out_ptr     = d_outf + NP * 3;
    } else if (out_size == NP * COUT) {          // output only
        centers_ptr = g_cscratch;                // resolved by device linker
        out_ptr     = d_outf;
        cudaMemcpyToSymbol(g_cscratch, &d_outf, 0, cudaMemcpyHostToDevice); // no-op safe? avoid
    } else {                                     // centers only
        centers_ptr = d_outf;
        out_ptr     = g_oscratch;
    }
    // NOTE: taking device-symbol addresses properly:
    if (out_size == NP * COUT) {
        cudaGetSymbolAddress((void**)&centers_ptr, g_cscratch);
        out_ptr = d_outf;
    } else if (out_size != NP * 3 + NP * COUT) {
        cudaGetSymbolAddress((void**)&out_ptr, g_oscratch);
        centers_ptr = d_outf;
    }

    prep_kernel<<<16, 256>>>(pos);
    dcconv_kernel<<<NP, 256>>>(chan, coef, centers_ptr, out_ptr);
}

// round 4
// speedup vs baseline: 1.2109x; 1.2109x over previous
#include <cuda_runtime.h>
#include <cuda_bf16.h>

#define NP   4096
#define KNN  32
#define CIN  16
#define COUT 32
#define NB   27      // 3*3*3 basis terms
#define NG   432     // CIN*NB
#define SURV_CAP 2048

__device__ float4 g_posq[NP];
__device__ float  g_cscratch[NP * 3];
__device__ float  g_oscratch[NP * COUT];

// ---------------------------------------------------------------------------
// LAPACK fp32 helpers (conventions of LAPACK >= 3.10) — validated in R2
// ---------------------------------------------------------------------------
__device__ __forceinline__ float slapy2f(float x, float y) {
    float xa = fabsf(x), ya = fabsf(y);
    float w = fmaxf(xa, ya), z = fminf(xa, ya);
    if (z == 0.f) return w;
    float t = z / w;
    return w * sqrtf(1.f + t * t);
}

__device__ __forceinline__ void slartgf(float f, float g, float* c, float* s, float* r) {
    if (g == 0.f)      { *c = 1.f; *s = 0.f; *r = f; }
    else if (f == 0.f) { *c = 0.f; *s = (g > 0.f) ? 1.f : -1.f; *r = fabsf(g); }
    else {
        float d = sqrtf(f * f + g * g);
        float p = 1.f / d;
        *c = fabsf(f) * p;
        *s = g * copysignf(p, f);
        *r = copysignf(d, f);
    }
}

__device__ void slaev2f(float a, float b, float c, float* rt1, float* rt2,
                        float* cs1, float* sn1) {
    float sm = a + c, df = a - c;
    float adf = fabsf(df);
    float tb = b + b, ab = fabsf(tb);
    float acmx, acmn;
    if (fabsf(a) > fabsf(c)) { acmx = a; acmn = c; } else { acmx = c; acmn = a; }
    float rt;
    if (adf > ab)      { float t = ab / adf; rt = adf * sqrtf(1.f + t * t); }
    else if (adf < ab) { float t = adf / ab; rt = ab * sqrtf(1.f + t * t); }
    else               rt = ab * sqrtf(2.f);
    int sgn1;
    if (sm < 0.f)      { *rt1 = 0.5f * (sm - rt); sgn1 = -1;
                         *rt2 = (acmx / *rt1) * acmn - (b / *rt1) * b; }
    else if (sm > 0.f) { *rt1 = 0.5f * (sm + rt); sgn1 = 1;
                         *rt2 = (acmx / *rt1) * acmn - (b / *rt1) * b; }
    else               { *rt1 = 0.5f * rt; *rt2 = -0.5f * rt; sgn1 = 1; }
    float cs; int sgn2;
    if (df >= 0.f) { cs = df + rt; sgn2 = 1; } else { cs = df - rt; sgn2 = -1; }
    float acs = fabsf(cs);
    if (acs > ab) {
        float ct = -tb / cs;
        *sn1 = 1.f / sqrtf(1.f + ct * ct);
        *cs1 = ct * *sn1;
    } else {
        if (ab == 0.f) { *cs1 = 1.f; *sn1 = 0.f; }
        else {
            float tn = -cs / tb;
            *cs1 = 1.f / sqrtf(1.f + tn * tn);
            *sn1 = tn * *cs1;
        }
    }
    if (sgn1 == sgn2) { float tn = *cs1; *cs1 = -*sn1; *sn1 = tn; }
}

__device__ void ssteqr3(float* D, float* E, float z[3][3]) {
    const float eps = 5.9604645e-08f, eps2 = eps * eps, safmin = 1.17549435e-38f;
    const int n = 3, nmaxit = 90;
    float d[4] = {0.f, D[0], D[1], D[2]};
    float e[3] = {0.f, E[0], E[1]};
    for (int i = 0; i < 3; ++i)
        for (int j = 0; j < 3; ++j) z[i][j] = (i == j) ? 1.f : 0.f;
    int jtot = 0, l1 = 1;
    float wc[3], ws[3];

    while (l1 <= n) {
        if (l1 > 1) e[l1 - 1] = 0.f;
        int m = n;
        for (int mm = l1; mm <= n - 1; ++mm) {
            float tst = fabsf(e[mm]);
            if (tst == 0.f) { m = mm; break; }
            if (tst <= (sqrtf(fabsf(d[mm])) * sqrtf(fabsf(d[mm + 1]))) * eps) {
                e[mm] = 0.f; m = mm; break;
            }
        }
        int l = l1;
        int lsv = l, lend = m, lendsv = lend;
        l1 = m + 1;
        if (lend == l) continue;
        if (fabsf(d[lend]) < fabsf(d[l])) { lend = lsv; l = lendsv; }

        if (lend > l) {
            for (;;) {
                int mq = lend;
                if (l != lend) {
                    for (int mi = l; mi <= lend - 1; ++mi) {
                        float tst = e[mi] * e[mi];
                        if (tst <= (eps2 * fabsf(d[mi])) * fabsf(d[mi + 1]) + safmin) {
                            mq = mi; break;
                        }
                    }
                }
                if (mq < lend) e[mq] = 0.f;
                float p = d[l];
                if (mq == l) { d[l] = p; if (++l <= lend) continue; break; }
                if (mq == l + 1) {
                    float rt1, rt2, c, s;
                    slaev2f(d[l], e[l], d[l + 1], &rt1, &rt2, &c, &s);
                    for (int i = 0; i < 3; ++i) {
                        float t = z[i][l];
                        z[i][l]     = c * t - s * z[i][l - 1];
                        z[i][l - 1] = s * t + c * z[i][l - 1];
                    }
                    d[l] = rt1; d[l + 1] = rt2; e[l] = 0.f;
                    l += 2;
                    if (l <= lend) continue;
                    break;
                }
                if (jtot == nmaxit) break;
                ++jtot;
                float g = (d[l + 1] - p) / (2.f * e[l]);
                float r = slapy2f(g, 1.f);
                g = d[mq] - p + (e[l] / (g + copysignf(r, g)));
                float s = 1.f, c = 1.f; p = 0.f;
                for (int i = mq - 1; i >= l; --i) {
                    float f = s * e[i], b = c * e[i];
                    slartgf(g, f, &c, &s, &r);
                    if (i != mq - 1) e[i + 1] = r;
                    g = d[i + 1] - p;
                    r = (d[i] - g) * s + 2.f * c * b;
                    p = s * r;
                    d[i + 1] = g + p;
                    g = c * r - b;
                    wc[i] = c; ws[i] = -s;
                }
                for (int j = mq - l; j >= 1; --j) {
                    float ct = wc[l + j - 1], st = ws[l + j - 1];
                    for (int i = 0; i < 3; ++i) {
                        float t = z[i][l + j - 1];
                        z[i][l + j - 1] = ct * t - st * z[i][l + j - 2];
                        z[i][l + j - 2] = st * t + ct * z[i][l + j - 2];
                    }
                }
                d[l] -= p;
                e[l] = g;
            }
        } else {
            for (;;) {
                int mq = lend;
                if (l != lend) {
                    for (int mi = l; mi >= lend + 1; --mi) {
                        float tst = e[mi - 1] * e[mi - 1];
                        if (tst <= (eps2 * fabsf(d[mi])) * fabsf(d[mi - 1]) + safmin) {
                            mq = mi; break;
                        }
                    }
                }
                if (mq > lend) e[mq - 1] = 0.f;
                float p = d[l];
                if (mq == l) { d[l] = p; if (--l >= lend) continue; break; }
                if (mq == l - 1) {
                    float rt1, rt2, c, s;
                    slaev2f(d[l - 1], e[l - 1], d[l], &rt1, &rt2, &c, &s);
                    for (int i = 0; i < 3; ++i) {
                        float t = z[i][l - 1];
                        z[i][l - 1] = c * t - s * z[i][l - 2];
                        z[i][l - 2] = s * t + c * z[i][l - 2];
                    }
                    d[l - 1] = rt1; d[l] = rt2; e[l - 1] = 0.f;
                    l -= 2;
                    if (l >= lend) continue;
                    break;
                }
                if (jtot == nmaxit) break;
                ++jtot;
                float g = (d[l - 1] - p) / (2.f * e[l - 1]);
                float r = slapy2f(g, 1.f);
                g = d[mq] - p + (e[l - 1] / (g + copysignf(r, g)));
                float s = 1.f, c = 1.f; p = 0.f;
                for (int i = mq; i <= l - 1; ++i) {
                    float f = s * e[i], b = c * e[i];
                    slartgf(g, f, &c, &s, &r);
                    if (i != mq) e[i - 1] = r;
                    g = d[i] - p;
                    r = (d[i + 1] - g) * s + 2.f * c * b;
                    p = s * r;
                    d[i] = g + p;
                    g = c * r - b;
                    wc[i] = c; ws[i] = s;
                }
                for (int j = 1; j <= l - mq; ++j) {
                    float ct = wc[mq + j - 1], st = ws[mq + j - 1];
                    for (int i = 0; i < 3; ++i) {
                        float t = z[i][mq + j - 1];
                        z[i][mq + j - 1] = ct * t - st * z[i][mq + j - 2];
                        z[i][mq + j - 2] = st * t + ct * z[i][mq + j - 2];
                    }
                }
                d[l] -= p;
                e[l - 1] = g;
            }
        }
    }
    for (int ii = 2; ii <= n; ++ii) {
        int i = ii - 1, k = i;
        float p = d[i];
        for (int j = ii; j <= n; ++j) if (d[j] < p) { k = j; p = d[j]; }
        if (k != i) {
            d[k] = d[i]; d[i] = p;
            for (int r2 = 0; r2 < 3; ++r2) {
                float t = z[r2][i - 1]; z[r2][i - 1] = z[r2][k - 1]; z[r2][k - 1] = t;
            }
        }
    }
}

__device__ void eigh3(const float A[6], float V[3][3]) {
    float a00 = A[0], a10 = A[1], a20 = A[2], a11 = A[3], a21 = A[4], a22 = A[5];
    float tau = 0.f, v2 = 0.f, e0, e1, d1 = a11, d2v = a22;
    float xnorm = fabsf(a20);
    if (xnorm == 0.f) { tau = 0.f; e0 = a10; e1 = a21; }
    else {
        float alpha = a10;
        float beta = -copysignf(slapy2f(alpha, xnorm), alpha);
        tau = (beta - alpha) / beta;
        v2 = a20 * (1.f / (alpha - beta));
        e0 = beta;
        float w0 = tau * a11 + tau * (a21 * v2);
        float w1 = tau * a21 + (tau * v2) * a22;
        float aw = -0.5f * tau * (w0 + w1 * v2);
        w0 += aw; w1 += aw * v2;
        d1  = (a11 - w0) - w0;
        e1  = (a21 - v2 * w0) - w1;
        d2v = (a22 - v2 * w1) - w1 * v2;
    }
    float d[3] = {a00, d1, d2v};
    float e[2] = {e0, e1};
    ssteqr3(d, e, V);
    if (tau != 0.f) {
        for (int j = 0; j < 3; ++j) {
            float s = V[1][j] + v2 * V[2][j];
            V[1][j] -= tau * s;
            V[2][j] -= tau * v2 * s;
        }
    }
}

// ---------------------------------------------------------------------------
// 64-bit warp min via two 32-bit REDUX.MIN (index lives in low bits -> exact
// tie-break: smallest d2, then smallest index). Keys are unique.
__device__ __forceinline__ unsigned long long warp_min64(unsigned long long k) {
    unsigned hi = (unsigned)(k >> 32), lo = (unsigned)k;
    unsigned mhi = __reduce_min_sync(0xffffffffu, hi);
    unsigned lo2 = (hi == mhi) ? lo : 0xffffffffu;
    unsigned mlo = __reduce_min_sync(0xffffffffu, lo2);
    return ((unsigned long long)mhi << 32) | mlo;
}

__global__ void prep_kernel(const float* __restrict__ pos) {
    int p = blockIdx.x * blockDim.x + threadIdx.x;
    if (p < NP) {
        float x = pos[3 * p], y = pos[3 * p + 1], z = pos[3 * p + 2];
        g_posq[p] = make_float4(x, y, z, x * x + y * y + z * z);
    }
}

__global__ __launch_bounds__(256)
void dcconv_kernel(const float* __restrict__ chan,
                   const float* __restrict__ coef,
                   float* __restrict__ centers_out,
                   float* __restrict__ out) {
    const int p = blockIdx.x;
    const int tid = threadIdx.x;
    const int lane = tid & 31;
    const int wid = tid >> 5;

    __shared__ unsigned long long s_surv[SURV_CAP];
    __shared__ unsigned long long s_b4[8];
    __shared__ int                s_cnt;
    __shared__ int                s_nbr[KNN];
    __shared__ float4             s_npos[KNN];
    __shared__ float              s_l[3][KNN];
    __shared__ float              s_center[3];
    __shared__ float              s_ev[3][3];
    __shared__ float              s_basis[KNN][NB];
    __shared__ float              s_feat[KNN][CIN];
    __shared__ float              s_G[NG];

    if (tid == 0) s_cnt = 0;

    // ---------- Phase 1a: all 4096 d2 keys, per-thread min -------------------
    const float4 pq = g_posq[p];
    unsigned long long keys[16];
#pragma unroll
    for (int j = 0; j < 16; ++j) {
        int cand = tid + (j << 8);
        float4 cq = g_posq[cand];
        float dot = pq.x * cq.x + pq.y * cq.y + pq.z * cq.z;
        float d2 = (pq.w + cq.w) - 2.f * dot;
        unsigned u = __float_as_uint(d2);
        u = (u & 0x80000000u) ? ~u : (u | 0x80000000u);
        keys[j] = ((unsigned long long)u << 32) | (unsigned)cand;
    }
    unsigned long long lmin = keys[0];
#pragma unroll
    for (int j = 1; j < 16; ++j) if (keys[j] < lmin) lmin = keys[j];

    // ---------- Phase 1b: bound B = max over warps of 4th-smallest lane-min --
    // Each warp exhibits 4 distinct keys <= its 4th-min, so >=32 keys <= B:
    // the exact top-32 all survive the filter key <= B.
    {
        unsigned long long h = lmin, w4 = 0;
#pragma unroll
        for (int r = 0; r < 4; ++r) {
            w4 = warp_min64(h);
            if (h == w4) h = ~0ULL;
        }
        if (lane == 0) s_b4[wid] = w4;
    }
    __syncthreads();
    unsigned long long B = s_b4[0];
#pragma unroll
    for (int i = 1; i < 8; ++i) if (s_b4[i] > B) B = s_b4[i];

    // ---------- Phase 1c: gather survivors ----------------------------------
#pragma unroll
    for (int j = 0; j < 16; ++j) {
        if (keys[j] <= B) {
            int idx = atomicAdd(&s_cnt, 1);
            if (idx < SURV_CAP) s_surv[idx] = keys[j];
        }
    }
    __syncthreads();
    int S = s_cnt < SURV_CAP ? s_cnt : SURV_CAP;

    // ---------- Phase 1d: exact top-32 over survivors (one warp) -------------
    if (wid == 0) {
        for (int r = 0; r < KNN; ++r) {
            unsigned long long m = ~0ULL; int mi = -1;
            for (int i = lane; i < S; i += 32) {
                unsigned long long v = s_surv[i];
                if (v < m) { m = v; mi = i; }
            }
            unsigned long long w = warp_min64(m);
            if (m == w && mi >= 0) {
                s_surv[mi] = ~0ULL;              // unique owner removes winner
                s_nbr[r] = (int)(w & 0xffffffffu);
            }
        }
    }
    __syncthreads();

    // ---------- Phase 2: center, local coords, covariance, eigh --------------
    if (tid < KNN) s_npos[tid] = g_posq[s_nbr[tid]];
    __syncthreads();
    if (tid == 0) {
        float cx = 0.f, cy = 0.f, cz = 0.f;
        for (int k = 0; k < KNN; ++k) { cx += s_npos[k].x; cy += s_npos[k].y; cz += s_npos[k].z; }
        cx /= (float)KNN; cy /= (float)KNN; cz /= (float)KNN;
        s_center[0] = cx; s_center[1] = cy; s_center[2] = cz;
        centers_out[3 * p]     = cx;
        centers_out[3 * p + 1] = cy;
        centers_out[3 * p + 2] = cz;
    }
    __syncthreads();
    if (tid < KNN) {
        s_l[0][tid] = s_npos[tid].x - s_center[0];
        s_l[1][tid] = s_npos[tid].y - s_center[1];
        s_l[2][tid] = s_npos[tid].z - s_center[2];
    }
    __syncthreads();
    if (tid == 0) {
        float A[6]; int idx = 0;
        for (int d = 0; d < 3; ++d)
            for (int e2 = d; e2 < 3; ++e2) {
                float s = 0.f;
                for (int k = 0; k < KNN; ++k) s += s_l[d][k] * s_l[e2][k];
                A[idx++] = s / (float)KNN;
            }
        float V[3][3];
        eigh3(A, V);
        for (int i = 0; i < 3; ++i)
            for (int j = 0; j < 3; ++j) s_ev[i][j] = V[i][j];
    }
    __syncthreads();

    // ---------- Phase 3: rotate, spherical coords, basis ---------------------
    if (tid < KNN) {
        float lx = s_l[0][tid], ly = s_l[1][tid], lz = s_l[2][tid];
        float x = lx * s_ev[0][0] + ly * s_ev[1][0] + lz * s_ev[2][0];
        float y = lx * s_ev[0][1] + ly * s_ev[1][1] + lz * s_ev[2][1];
        float z = lx * s_ev[0][2] + ly * s_ev[1][2] + lz * s_ev[2][2];
        float r = sqrtf(x * x + y * y + z * z);
        float ct = z / (r + 1e-8f);
        ct = fminf(fmaxf(ct, -1.f + 1e-6f), 1.f - 1e-6f);
        float theta = acosf(ct);
        float phi = atan2f(y, x);
        float rb[3] = {1.f, r, r * r};
        float tb[3] = {1.f, cosf(theta), cosf(2.f * theta)};
        float pb[3] = {1.f, cosf(phi), cosf(2.f * phi)};
#pragma unroll
        for (int n = 0; n < 3; ++n)
#pragma unroll
            for (int l = 0; l < 3; ++l)
#pragma unroll
                for (int m = 0; m < 3; ++m)
                    s_basis[tid][n * 9 + l * 3 + m] = (rb[n] * tb[l]) * pb[m];
    }
    {
        int k = tid >> 4, c = tid & 15;
        s_feat[k][c]      = chan[s_nbr[k] * CIN + c];
        s_feat[k + 16][c] = chan[s_nbr[k + 16] * CIN + c];
    }
    __syncthreads();

    // ---------- Phase 4: G[c*27+nlm] = sum_k basis[k][nlm]*feat[k][c] --------
    for (int j = tid; j < NG; j += 256) {
        int c = j / NB, nlm = j - c * NB;
        float s = 0.f;
#pragma unroll
        for (int k = 0; k < KNN; ++k) s += s_basis[k][nlm] * s_feat[k][c];
        s_G[j] = s;
    }
    __syncthreads();

    // ---------- Phase 5: out[o] = sum_j coef[o*432+j] * G[j] -----------------
    {
        int o = tid >> 3, part = tid & 7;
        const float* cf = coef + o * NG;
        float s = 0.f;
        for (int j = part; j < NG; j += 8) s += cf[j] * s_G[j];
#pragma unroll
        for (int off = 4; off; off >>= 1)
            s += __shfl_down_sync(0xffffffffu, s, off);
        if (part == 0) out[p * COUT + o] = s;
    }
}

extern "C" void kernel_launch(void* const* d_in, const int* in_sizes, int n_in,
                              void* d_out, int out_size) {
    const float* pos  = (const float*)d_in[0];
    const float* chan = (const float*)d_in[1];
    const float* coef = (const float*)d_in[3];

    float* d_outf = (float*)d_out;
    float* centers_ptr;
    float* out_ptr;
    if (out_size == NP * 3 + NP * COUT) {
        centers_ptr = d_outf;
        out_ptr     = d_outf + NP * 3;
    } else if (out_size == NP * COUT) {
        cudaGetSymbolAddress((void**)&centers_ptr, g_cscratch);
        out_ptr = d_outf;
    } else {
        centers_ptr = d_outf;
        cudaGetSymbolAddress((void**)&out_ptr, g_oscratch);
    }

    prep_kernel<<<16, 256>>>(pos);
    dcconv_kernel<<<NP, 256>>>(chan, coef, centers_ptr, out_ptr);
}

// round 5
// speedup vs baseline: 1.8924x; 1.5627x over previous
#include <cuda_runtime.h>
#include <cuda_bf16.h>

#define NP   4096
#define KNN  32
#define CIN  16
#define COUT 32
#define NB   27
#define NG   432
#define SURV_CAP 2048

__device__ float4 g_posq[NP];
__device__ int    g_nbr[NP * KNN];
__device__ float  g_coefT[108 * 128];     // [j/4][o][j%4]
__device__ float  g_cscratch[NP * 3];
__device__ float  g_oscratch[NP * COUT];

// ---------------------------------------------------------------------------
// LAPACK fp32 helpers (LAPACK >= 3.10 conventions) — validated R2/R3
// ---------------------------------------------------------------------------
__device__ __forceinline__ float slapy2f(float x, float y) {
    float xa = fabsf(x), ya = fabsf(y);
    float w = fmaxf(xa, ya), z = fminf(xa, ya);
    if (z == 0.f) return w;
    float t = z / w;
    return w * sqrtf(1.f + t * t);
}

__device__ __forceinline__ void slartgf(float f, float g, float* c, float* s, float* r) {
    if (g == 0.f)      { *c = 1.f; *s = 0.f; *r = f; }
    else if (f == 0.f) { *c = 0.f; *s = (g > 0.f) ? 1.f : -1.f; *r = fabsf(g); }
    else {
        float d = sqrtf(f * f + g * g);
        float p = 1.f / d;
        *c = fabsf(f) * p;
        *s = g * copysignf(p, f);
        *r = copysignf(d, f);
    }
}

__device__ void slaev2f(float a, float b, float c, float* rt1, float* rt2,
                        float* cs1, float* sn1) {
    float sm = a + c, df = a - c;
    float adf = fabsf(df);
    float tb = b + b, ab = fabsf(tb);
    float acmx, acmn;
    if (fabsf(a) > fabsf(c)) { acmx = a; acmn = c; } else { acmx = c; acmn = a; }
    float rt;
    if (adf > ab)      { float t = ab / adf; rt = adf * sqrtf(1.f + t * t); }
    else if (adf < ab) { float t = adf / ab; rt = ab * sqrtf(1.f + t * t); }
    else               rt = ab * sqrtf(2.f);
    int sgn1;
    if (sm < 0.f)      { *rt1 = 0.5f * (sm - rt); sgn1 = -1;
                         *rt2 = (acmx / *rt1) * acmn - (b / *rt1) * b; }
    else if (sm > 0.f) { *rt1 = 0.5f * (sm + rt); sgn1 = 1;
                         *rt2 = (acmx / *rt1) * acmn - (b / *rt1) * b; }
    else               { *rt1 = 0.5f * rt; *rt2 = -0.5f * rt; sgn1 = 1; }
    float cs; int sgn2;
    if (df >= 0.f) { cs = df + rt; sgn2 = 1; } else { cs = df - rt; sgn2 = -1; }
    float acs = fabsf(cs);
    if (acs > ab) {
        float ct = -tb / cs;
        *sn1 = 1.f / sqrtf(1.f + ct * ct);
        *cs1 = ct * *sn1;
    } else {
        if (ab == 0.f) { *cs1 = 1.f; *sn1 = 0.f; }
        else {
            float tn = -cs / tb;
            *cs1 = 1.f / sqrtf(1.f + tn * tn);
            *sn1 = tn * *cs1;
        }
    }
    if (sgn1 == sgn2) { float tn = *cs1; *cs1 = -*sn1; *sn1 = tn; }
}

__device__ void ssteqr3(float* D, float* E, float z[3][3]) {
    const float eps = 5.9604645e-08f, eps2 = eps * eps, safmin = 1.17549435e-38f;
    const int n = 3, nmaxit = 90;
    float d[4] = {0.f, D[0], D[1], D[2]};
    float e[3] = {0.f, E[0], E[1]};
    for (int i = 0; i < 3; ++i)
        for (int j = 0; j < 3; ++j) z[i][j] = (i == j) ? 1.f : 0.f;
    int jtot = 0, l1 = 1;
    float wc[3], ws[3];

    while (l1 <= n) {
        if (l1 > 1) e[l1 - 1] = 0.f;
        int m = n;
        for (int mm = l1; mm <= n - 1; ++mm) {
            float tst = fabsf(e[mm]);
            if (tst == 0.f) { m = mm; break; }
            if (tst <= (sqrtf(fabsf(d[mm])) * sqrtf(fabsf(d[mm + 1]))) * eps) {
                e[mm] = 0.f; m = mm; break;
            }
        }
        int l = l1;
        int lsv = l, lend = m, lendsv = lend;
        l1 = m + 1;
        if (lend == l) continue;
        if (fabsf(d[lend]) < fabsf(d[l])) { lend = lsv; l = lendsv; }

        if (lend > l) {
            for (;;) {
                int mq = lend;
                if (l != lend) {
                    for (int mi = l; mi <= lend - 1; ++mi) {
                        float tst = e[mi] * e[mi];
                        if (tst <= (eps2 * fabsf(d[mi])) * fabsf(d[mi + 1]) + safmin) {
                            mq = mi; break;
                        }
                    }
                }
                if (mq < lend) e[mq] = 0.f;
                float p = d[l];
                if (mq == l) { d[l] = p; if (++l <= lend) continue; break; }
                if (mq == l + 1) {
                    float rt1, rt2, c, s;
                    slaev2f(d[l], e[l], d[l + 1], &rt1, &rt2, &c, &s);
                    for (int i = 0; i < 3; ++i) {
                        float t = z[i][l];
                        z[i][l]     = c * t - s * z[i][l - 1];
                        z[i][l - 1] = s * t + c * z[i][l - 1];
                    }
                    d[l] = rt1; d[l + 1] = rt2; e[l] = 0.f;
                    l += 2;
                    if (l <= lend) continue;
                    break;
                }
                if (jtot == nmaxit) break;
                ++jtot;
                float g = (d[l + 1] - p) / (2.f * e[l]);
                float r = slapy2f(g, 1.f);
                g = d[mq] - p + (e[l] / (g + copysignf(r, g)));
                float s = 1.f, c = 1.f; p = 0.f;
                for (int i = mq - 1; i >= l; --i) {
                    float f = s * e[i], b = c * e[i];
                    slartgf(g, f, &c, &s, &r);
                    if (i != mq - 1) e[i + 1] = r;
                    g = d[i + 1] - p;
                    r = (d[i] - g) * s + 2.f * c * b;
                    p = s * r;
                    d[i + 1] = g + p;
                    g = c * r - b;
                    wc[i] = c; ws[i] = -s;
                }
                for (int j = mq - l; j >= 1; --j) {
                    float ct = wc[l + j - 1], st = ws[l + j - 1];
                    for (int i = 0; i < 3; ++i) {
                        float t = z[i][l + j - 1];
                        z[i][l + j - 1] = ct * t - st * z[i][l + j - 2];
                        z[i][l + j - 2] = st * t + ct * z[i][l + j - 2];
                    }
                }
                d[l] -= p;
                e[l] = g;
            }
        } else {
            for (;;) {
                int mq = lend;
                if (l != lend) {
                    for (int mi = l; mi >= lend + 1; --mi) {
                        float tst = e[mi - 1] * e[mi - 1];
                        if (tst <= (eps2 * fabsf(d[mi])) * fabsf(d[mi - 1]) + safmin) {
                            mq = mi; break;
                        }
                    }
                }
                if (mq > lend) e[mq - 1] = 0.f;
                float p = d[l];
                if (mq == l) { d[l] = p; if (--l >= lend) continue; break; }
                if (mq == l - 1) {
                    float rt1, rt2, c, s;
                    slaev2f(d[l - 1], e[l - 1], d[l], &rt1, &rt2, &c, &s);
                    for (int i = 0; i < 3; ++i) {
                        float t = z[i][l - 1];
                        z[i][l - 1] = c * t - s * z[i][l - 2];
                        z[i][l - 2] = s * t + c * z[i][l - 2];
                    }
                    d[l - 1] = rt1; d[l] = rt2; e[l - 1] = 0.f;
                    l -= 2;
                    if (l >= lend) continue;
                    break;
                }
                if (jtot == nmaxit) break;
                ++jtot;
                float g = (d[l - 1] - p) / (2.f * e[l - 1]);
                float r = slapy2f(g, 1.f);
                g = d[mq] - p + (e[l - 1] / (g + copysignf(r, g)));
                float s = 1.f, c = 1.f; p = 0.f;
                for (int i = mq; i <= l - 1; ++i) {
                    float f = s * e[i], b = c * e[i];
                    slartgf(g, f, &c, &s, &r);
                    if (i != mq) e[i - 1] = r;
                    g = d[i] - p;
                    r = (d[i + 1] - g) * s + 2.f * c * b;
                    p = s * r;
                    d[i] = g + p;
                    g = c * r - b;
                    wc[i] = c; ws[i] = s;
                }
                for (int j = 1; j <= l - mq; ++j) {
                    float ct = wc[mq + j - 1], st = ws[mq + j - 1];
                    for (int i = 0; i < 3; ++i) {
                        float t = z[i][mq + j - 1];
                        z[i][mq + j - 1] = ct * t - st * z[i][mq + j - 2];
                        z[i][mq + j - 2] = st * t + ct * z[i][mq + j - 2];
                    }
                }
                d[l] -= p;
                e[l - 1] = g;
            }
        }
    }
    for (int ii = 2; ii <= n; ++ii) {
        int i = ii - 1, k = i;
        float p = d[i];
        for (int j = ii; j <= n; ++j) if (d[j] < p) { k = j; p = d[j]; }
        if (k != i) {
            d[k] = d[i]; d[i] = p;
            for (int r2 = 0; r2 < 3; ++r2) {
                float t = z[r2][i - 1]; z[r2][i - 1] = z[r2][k - 1]; z[r2][k - 1] = t;
            }
        }
    }
}

__device__ void eigh3(const float A[6], float V[3][3]) {
    float a00 = A[0], a10 = A[1], a20 = A[2], a11 = A[3], a21 = A[4], a22 = A[5];
    float tau = 0.f, v2 = 0.f, e0, e1, d1 = a11, d2v = a22;
    float xnorm = fabsf(a20);
    if (xnorm == 0.f) { tau = 0.f; e0 = a10; e1 = a21; }
    else {
        float alpha = a10;
        float beta = -copysignf(slapy2f(alpha, xnorm), alpha);
        tau = (beta - alpha) / beta;
        v2 = a20 * (1.f / (alpha - beta));
        e0 = beta;
        float w0 = tau * a11 + tau * (a21 * v2);
        float w1 = tau * a21 + (tau * v2) * a22;
        float aw = -0.5f * tau * (w0 + w1 * v2);
        w0 += aw; w1 += aw * v2;
        d1  = (a11 - w0) - w0;
        e1  = (a21 - v2 * w0) - w1;
        d2v = (a22 - v2 * w1) - w1 * v2;
    }
    float d[3] = {a00, d1, d2v};
    float e[2] = {e0, e1};
    ssteqr3(d, e, V);
    if (tau != 0.f) {
        for (int j = 0; j < 3; ++j) {
            float s = V[1][j] + v2 * V[2][j];
            V[1][j] -= tau * s;
            V[2][j] -= tau * v2 * s;
        }
    }
}

// ---------------------------------------------------------------------------
__device__ __forceinline__ unsigned long long warp_min64(unsigned long long k) {
    unsigned hi = (unsigned)(k >> 32), lo = (unsigned)k;
    unsigned mhi = __reduce_min_sync(0xffffffffu, hi);
    unsigned lo2 = (hi == mhi) ? lo : 0xffffffffu;
    unsigned mlo = __reduce_min_sync(0xffffffffu, lo2);
    return ((unsigned long long)mhi << 32) | mlo;
}

__global__ void prep_kernel(const float* __restrict__ pos) {
    int p = blockIdx.x * blockDim.x + threadIdx.x;
    if (p < NP) {
        float x = pos[3 * p], y = pos[3 * p + 1], z = pos[3 * p + 2];
        g_posq[p] = make_float4(x, y, z, x * x + y * y + z * z);
    }
}

__global__ void transpose_coef_kernel(const float* __restrict__ coef) {
    int i = blockIdx.x * blockDim.x + threadIdx.x;     // over COUT*NG = 13824
    if (i < COUT * NG) {
        int o = i / NG, j = i - o * NG;
        g_coefT[(j >> 2) * 128 + o * 4 + (j & 3)] = coef[i];
    }
}

// ---------------------------------------------------------------------------
// Kernel 1: exact kNN (top-32 by ascending d2, tie -> lower index)
// ---------------------------------------------------------------------------
__global__ __launch_bounds__(256)
void knn_kernel() {
    const int p = blockIdx.x;
    const int tid = threadIdx.x;
    const int lane = tid & 31;
    const int wid = tid >> 5;

    __shared__ unsigned long long s_surv[SURV_CAP];
    __shared__ unsigned long long s_b4[8];
    __shared__ int s_cnt;

    if (tid == 0) s_cnt = 0;

    const float4 pq = g_posq[p];
    unsigned long long keys[16];
#pragma unroll
    for (int j = 0; j < 16; ++j) {
        int cand = tid + (j << 8);
        float4 cq = g_posq[cand];
        float dot = pq.x * cq.x + pq.y * cq.y + pq.z * cq.z;
        float d2 = (pq.w + cq.w) - 2.f * dot;
        unsigned u = __float_as_uint(d2);
        u = (u & 0x80000000u) ? ~u : (u | 0x80000000u);
        keys[j] = ((unsigned long long)u << 32) | (unsigned)cand;
    }
    unsigned long long lmin = keys[0];
#pragma unroll
    for (int j = 1; j < 16; ++j) if (keys[j] < lmin) lmin = keys[j];

    // bound B = max over warps of warp-4th-smallest lane-min (>=32 keys <= B)
    {
        unsigned long long h = lmin, w4 = 0;
#pragma unroll
        for (int r = 0; r < 4; ++r) {
            w4 = warp_min64(h);
            if (h == w4) h = ~0ULL;
        }
        if (lane == 0) s_b4[wid] = w4;
    }
    __syncthreads();
    unsigned long long B = s_b4[0];
#pragma unroll
    for (int i = 1; i < 8; ++i) if (s_b4[i] > B) B = s_b4[i];

#pragma unroll
    for (int j = 0; j < 16; ++j) {
        if (keys[j] <= B) {
            int idx = atomicAdd(&s_cnt, 1);
            if (idx < SURV_CAP) s_surv[idx] = keys[j];
        }
    }
    __syncthreads();

    if (wid != 0) return;           // only warp 0 extracts

    int S = s_cnt < SURV_CAP ? s_cnt : SURV_CAP;
    for (int r = 0; r < KNN; ++r) {
        unsigned long long m = ~0ULL; int mi = -1;
        for (int i = lane; i < S; i += 32) {
            unsigned long long v = s_surv[i];
            if (v < m) { m = v; mi = i; }
        }
        unsigned long long w = warp_min64(m);
        if (m == w && mi >= 0) s_surv[mi] = ~0ULL;   // unique owner removes it
        if (lane == 0) g_nbr[p * KNN + r] = (int)(w & 0xffffffffu);
    }
}

// ---------------------------------------------------------------------------
// Kernel 2: per-point conv, one warp per point, no block barriers
// ---------------------------------------------------------------------------
__global__ __launch_bounds__(256)
void conv_kernel(const float* __restrict__ chan,
                 float* __restrict__ centers_out,
                 float* __restrict__ out) {
    const int tid = threadIdx.x;
    const int lane = tid & 31;
    const int wid = tid >> 5;
    const int p = blockIdx.x * 8 + wid;

    __shared__ float s_basis[8][32][28];
    __shared__ float s_G[8][448];

    const int nb = g_nbr[p * KNN + lane];
    const float4 q = g_posq[nb];

    // center (butterfly sum -> identical value on all lanes), exact /32
    float cx = q.x, cy = q.y, cz = q.z;
#pragma unroll
    for (int off = 16; off; off >>= 1) {
        cx += __shfl_xor_sync(0xffffffffu, cx, off);
        cy += __shfl_xor_sync(0xffffffffu, cy, off);
        cz += __shfl_xor_sync(0xffffffffu, cz, off);
    }
    cx *= 0.03125f; cy *= 0.03125f; cz *= 0.03125f;
    if (lane == 0) {
        centers_out[3 * p]     = cx;
        centers_out[3 * p + 1] = cy;
        centers_out[3 * p + 2] = cz;
    }

    const float lx = q.x - cx, ly = q.y - cy, lz = q.z - cz;

    // covariance (6 butterfly reductions), exact /32
    float c00 = lx * lx, c01 = lx * ly, c02 = lx * lz;
    float c11 = ly * ly, c12 = ly * lz, c22 = lz * lz;
#pragma unroll
    for (int off = 16; off; off >>= 1) {
        c00 += __shfl_xor_sync(0xffffffffu, c00, off);
        c01 += __shfl_xor_sync(0xffffffffu, c01, off);
        c02 += __shfl_xor_sync(0xffffffffu, c02, off);
        c11 += __shfl_xor_sync(0xffffffffu, c11, off);
        c12 += __shfl_xor_sync(0xffffffffu, c12, off);
        c22 += __shfl_xor_sync(0xffffffffu, c22, off);
    }
    c00 *= 0.03125f; c01 *= 0.03125f; c02 *= 0.03125f;
    c11 *= 0.03125f; c12 *= 0.03125f; c22 *= 0.03125f;

    // eigh on lane 0, broadcast 9 entries
    float v00, v01, v02, v10, v11, v12, v20, v21, v22;
    if (lane == 0) {
        float A[6] = {c00, c01, c02, c11, c12, c22};
        float V[3][3];
        eigh3(A, V);
        v00 = V[0][0]; v01 = V[0][1]; v02 = V[0][2];
        v10 = V[1][0]; v11 = V[1][1]; v12 = V[1][2];
        v20 = V[2][0]; v21 = V[2][1]; v22 = V[2][2];
    }
    v00 = __shfl_sync(0xffffffffu, v00, 0); v01 = __shfl_sync(0xffffffffu, v01, 0);
    v02 = __shfl_sync(0xffffffffu, v02, 0); v10 = __shfl_sync(0xffffffffu, v10, 0);
    v11 = __shfl_sync(0xffffffffu, v11, 0); v12 = __shfl_sync(0xffffffffu, v12, 0);
    v20 = __shfl_sync(0xffffffffu, v20, 0); v21 = __shfl_sync(0xffffffffu, v21, 0);
    v22 = __shfl_sync(0xffffffffu, v22, 0);

    // rotate into PCA frame, spherical coords, 27 basis values
    {
        float x = lx * v00 + ly * v10 + lz * v20;
        float y = lx * v01 + ly * v11 + lz * v21;
        float z = lx * v02 + ly * v12 + lz * v22;
        float r = sqrtf(x * x + y * y + z * z);
        float ct = z / (r + 1e-8f);
        ct = fminf(fmaxf(ct, -1.f + 1e-6f), 1.f - 1e-6f);
        float theta = acosf(ct);
        float phi = atan2f(y, x);
        float rb[3] = {1.f, r, r * r};
        float tb[3] = {1.f, cosf(theta), cosf(2.f * theta)};
        float pb[3] = {1.f, cosf(phi), cosf(2.f * phi)};
#pragma unroll
        for (int n = 0; n < 3; ++n)
#pragma unroll
            for (int l = 0; l < 3; ++l)
#pragma unroll
                for (int m = 0; m < 3; ++m)
                    s_basis[wid][lane][n * 9 + l * 3 + m] = (rb[n] * tb[l]) * pb[m];
        s_basis[wid][lane][27] = 0.f;    // pad (read by half=1 float4 path)
    }
    __syncwarp();

    // phase 4: G[c*27+nlm] = sum_k basis[k][nlm]*feat[k][c]
    // lane -> (c = lane>>1, half = lane&1): half0 handles nlm 0..15, half1 16..27(pad)
    {
        const int c = lane >> 1;
        const int half = lane & 1;
        float acc[16];
#pragma unroll
        for (int i = 0; i < 16; ++i) acc[i] = 0.f;

        for (int k = 0; k < KNN; ++k) {
            int ik = __shfl_sync(0xffffffffu, nb, k);
            float fv = __ldg(&chan[ik * CIN + c]);
            const float* row = &s_basis[wid][k][0];
            if (half == 0) {
                float4 b0 = *(const float4*)(row);
                float4 b1 = *(const float4*)(row + 4);
                float4 b2 = *(const float4*)(row + 8);
                float4 b3 = *(const float4*)(row + 12);
                acc[0]  += b0.x * fv; acc[1]  += b0.y * fv; acc[2]  += b0.z * fv; acc[3]  += b0.w * fv;
                acc[4]  += b1.x * fv; acc[5]  += b1.y * fv; acc[6]  += b1.z * fv; acc[7]  += b1.w * fv;
                acc[8]  += b2.x * fv; acc[9]  += b2.y * fv; acc[10] += b2.z * fv; acc[11] += b2.w * fv;
                acc[12] += b3.x * fv; acc[13] += b3.y * fv; acc[14] += b3.z * fv; acc[15] += b3.w * fv;
            } else {
                float4 b0 = *(const float4*)(row + 16);
                float4 b1 = *(const float4*)(row + 20);
                float4 b2 = *(const float4*)(row + 24);
                acc[0]  += b0.x * fv; acc[1]  += b0.y * fv; acc[2]  += b0.z * fv; acc[3]  += b0.w * fv;
                acc[4]  += b1.x * fv; acc[5]  += b1.y * fv; acc[6]  += b1.z * fv; acc[7]  += b1.w * fv;
                acc[8]  += b2.x * fv; acc[9]  += b2.y * fv; acc[10] += b2.z * fv;
            }
        }
        if (half == 0) {
#pragma unroll
            for (int i = 0; i < 16; ++i) s_G[wid][c * 27 + i] = acc[i];
        } else {
#pragma unroll
            for (int i = 0; i < 11; ++i) s_G[wid][c * 27 + 16 + i] = acc[i];
        }
    }
    __syncwarp();

    // phase 5: out[o=lane] = sum_j coefT[j][o] * G[j], coalesced float4 loads
    {
        float a0 = 0.f, a1 = 0.f, a2 = 0.f, a3 = 0.f;
        const float* gT = g_coefT + lane * 4;
        const float* gw = &s_G[wid][0];
#pragma unroll 4
        for (int t = 0; t < 108; ++t) {
            float4 cf = *(const float4*)(gT + t * 128);
            float4 gv = *(const float4*)(gw + t * 4);
            a0 += cf.x * gv.x;
            a1 += cf.y * gv.y;
            a2 += cf.z * gv.z;
            a3 += cf.w * gv.w;
        }
        out[p * COUT + lane] = (a0 + a1) + (a2 + a3);
    }
}

extern "C" void kernel_launch(void* const* d_in, const int* in_sizes, int n_in,
                              void* d_out, int out_size) {
    const float* pos  = (const float*)d_in[0];
    const float* chan = (const float*)d_in[1];
    const float* coef = (const float*)d_in[3];

    float* d_outf = (float*)d_out;
    float* centers_ptr;
    float* out_ptr;
    if (out_size == NP * 3 + NP * COUT) {
        centers_ptr = d_outf;
        out_ptr     = d_outf + NP * 3;
    } else if (out_size == NP * COUT) {
        cudaGetSymbolAddress((void**)&centers_ptr, g_cscratch);
        out_ptr = d_outf;
    } else {
        centers_ptr = d_outf;
        cudaGetSymbolAddress((void**)&out_ptr, g_oscratch);
    }

    prep_kernel<<<16, 256>>>(pos);
    transpose_coef_kernel<<<54, 256>>>(coef);
    knn_kernel<<<NP, 256>>>();
    conv_kernel<<<NP / 8, 256>>>(chan, centers_ptr, out_ptr);
}

// round 6
// speedup vs baseline: 2.4777x; 1.3093x over previous
#include <cuda_runtime.h>
#include <cuda_bf16.h>

#define NP   4096
#define KNN  32
#define CIN  16
#define COUT 32
#define NB   27
#define NG   432
#define QB   8        // queries per knn block
#define SCAP 384      // survivor cap per query

__device__ float4 g_posq[NP];
__device__ int    g_nbr[NP * KNN];
__device__ float  g_coefT[108 * 128];     // [j/4][o][j%4]
__device__ float  g_cscratch[NP * 3];
__device__ float  g_oscratch[NP * COUT];

// ---------------------------------------------------------------------------
// LAPACK fp32 helpers (LAPACK >= 3.10 conventions) — validated R2..R4
// ---------------------------------------------------------------------------
__device__ __forceinline__ float slapy2f(float x, float y) {
    float xa = fabsf(x), ya = fabsf(y);
    float w = fmaxf(xa, ya), z = fminf(xa, ya);
    if (z == 0.f) return w;
    float t = z / w;
    return w * sqrtf(1.f + t * t);
}

__device__ __forceinline__ void slartgf(float f, float g, float* c, float* s, float* r) {
    if (g == 0.f)      { *c = 1.f; *s = 0.f; *r = f; }
    else if (f == 0.f) { *c = 0.f; *s = (g > 0.f) ? 1.f : -1.f; *r = fabsf(g); }
    else {
        float d = sqrtf(f * f + g * g);
        float p = 1.f / d;
        *c = fabsf(f) * p;
        *s = g * copysignf(p, f);
        *r = copysignf(d, f);
    }
}

__device__ void slaev2f(float a, float b, float c, float* rt1, float* rt2,
                        float* cs1, float* sn1) {
    float sm = a + c, df = a - c;
    float adf = fabsf(df);
    float tb = b + b, ab = fabsf(tb);
    float acmx, acmn;
    if (fabsf(a) > fabsf(c)) { acmx = a; acmn = c; } else { acmx = c; acmn = a; }
    float rt;
    if (adf > ab)      { float t = ab / adf; rt = adf * sqrtf(1.f + t * t); }
    else if (adf < ab) { float t = adf / ab; rt = ab * sqrtf(1.f + t * t); }
    else               rt = ab * sqrtf(2.f);
    int sgn1;
    if (sm < 0.f)      { *rt1 = 0.5f * (sm - rt); sgn1 = -1;
                         *rt2 = (acmx / *rt1) * acmn - (b / *rt1) * b; }
    else if (sm > 0.f) { *rt1 = 0.5f * (sm + rt); sgn1 = 1;
                         *rt2 = (acmx / *rt1) * acmn - (b / *rt1) * b; }
    else               { *rt1 = 0.5f * rt; *rt2 = -0.5f * rt; sgn1 = 1; }
    float cs; int sgn2;
    if (df >= 0.f) { cs = df + rt; sgn2 = 1; } else { cs = df - rt; sgn2 = -1; }
    float acs = fabsf(cs);
    if (acs > ab) {
        float ct = -tb / cs;
        *sn1 = 1.f / sqrtf(1.f + ct * ct);
        *cs1 = ct * *sn1;
    } else {
        if (ab == 0.f) { *cs1 = 1.f; *sn1 = 0.f; }
        else {
            float tn = -cs / tb;
            *cs1 = 1.f / sqrtf(1.f + tn * tn);
            *sn1 = tn * *cs1;
        }
    }
    if (sgn1 == sgn2) { float tn = *cs1; *cs1 = -*sn1; *sn1 = tn; }
}

__device__ void ssteqr3(float* D, float* E, float z[3][3]) {
    const float eps = 5.9604645e-08f, eps2 = eps * eps, safmin = 1.17549435e-38f;
    const int n = 3, nmaxit = 90;
    float d[4] = {0.f, D[0], D[1], D[2]};
    float e[3] = {0.f, E[0], E[1]};
    for (int i = 0; i < 3; ++i)
        for (int j = 0; j < 3; ++j) z[i][j] = (i == j) ? 1.f : 0.f;
    int jtot = 0, l1 = 1;
    float wc[3], ws[3];

    while (l1 <= n) {
        if (l1 > 1) e[l1 - 1] = 0.f;
        int m = n;
        for (int mm = l1; mm <= n - 1; ++mm) {
            float tst = fabsf(e[mm]);
            if (tst == 0.f) { m = mm; break; }
            if (tst <= (sqrtf(fabsf(d[mm])) * sqrtf(fabsf(d[mm + 1]))) * eps) {
                e[mm] = 0.f; m = mm; break;
            }
        }
        int l = l1;
        int lsv = l, lend = m, lendsv = lend;
        l1 = m + 1;
        if (lend == l) continue;
        if (fabsf(d[lend]) < fabsf(d[l])) { lend = lsv; l = lendsv; }

        if (lend > l) {
            for (;;) {
                int mq = lend;
                if (l != lend) {
                    for (int mi = l; mi <= lend - 1; ++mi) {
                        float tst = e[mi] * e[mi];
                        if (tst <= (eps2 * fabsf(d[mi])) * fabsf(d[mi + 1]) + safmin) {
                            mq = mi; break;
                        }
                    }
                }
                if (mq < lend) e[mq] = 0.f;
                float p = d[l];
                if (mq == l) { d[l] = p; if (++l <= lend) continue; break; }
                if (mq == l + 1) {
                    float rt1, rt2, c, s;
                    slaev2f(d[l], e[l], d[l + 1], &rt1, &rt2, &c, &s);
                    for (int i = 0; i < 3; ++i) {
                        float t = z[i][l];
                        z[i][l]     = c * t - s * z[i][l - 1];
                        z[i][l - 1] = s * t + c * z[i][l - 1];
                    }
                    d[l] = rt1; d[l + 1] = rt2; e[l] = 0.f;
                    l += 2;
                    if (l <= lend) continue;
                    break;
                }
                if (jtot == nmaxit) break;
                ++jtot;
                float g = (d[l + 1] - p) / (2.f * e[l]);
                float r = slapy2f(g, 1.f);
                g = d[mq] - p + (e[l] / (g + copysignf(r, g)));
                float s = 1.f, c = 1.f; p = 0.f;
                for (int i = mq - 1; i >= l; --i) {
                    float f = s * e[i], b = c * e[i];
                    slartgf(g, f, &c, &s, &r);
                    if (i != mq - 1) e[i + 1] = r;
                    g = d[i + 1] - p;
                    r = (d[i] - g) * s + 2.f * c * b;
                    p = s * r;
                    d[i + 1] = g + p;
                    g = c * r - b;
                    wc[i] = c; ws[i] = -s;
                }
                for (int j = mq - l; j >= 1; --j) {
                    float ct = wc[l + j - 1], st = ws[l + j - 1];
                    for (int i = 0; i < 3; ++i) {
                        float t = z[i][l + j - 1];
                        z[i][l + j - 1] = ct * t - st * z[i][l + j - 2];
                        z[i][l + j - 2] = st * t + ct * z[i][l + j - 2];
                    }
                }
                d[l] -= p;
                e[l] = g;
            }
        } else {
            for (;;) {
                int mq = lend;
                if (l != lend) {
                    for (int mi = l; mi >= lend + 1; --mi) {
                        float tst = e[mi - 1] * e[mi - 1];
                        if (tst <= (eps2 * fabsf(d[mi])) * fabsf(d[mi - 1]) + safmin) {
                            mq = mi; break;
                        }
                    }
                }
                if (mq > lend) e[mq - 1] = 0.f;
                float p = d[l];
                if (mq == l) { d[l] = p; if (--l >= lend) continue; break; }
                if (mq == l - 1) {
                    float rt1, rt2, c, s;
                    slaev2f(d[l - 1], e[l - 1], d[l], &rt1, &rt2, &c, &s);
                    for (int i = 0; i < 3; ++i) {
                        float t = z[i][l - 1];
                        z[i][l - 1] = c * t - s * z[i][l - 2];
                        z[i][l - 2] = s * t + c * z[i][l - 2];
                    }
                    d[l - 1] = rt1; d[l] = rt2; e[l - 1] = 0.f;
                    l -= 2;
                    if (l >= lend) continue;
                    break;
                }
                if (jtot == nmaxit) break;
                ++jtot;
                float g = (d[l - 1] - p) / (2.f * e[l - 1]);
                float r = slapy2f(g, 1.f);
                g = d[mq] - p + (e[l - 1] / (g + copysignf(r, g)));
                float s = 1.f, c = 1.f; p = 0.f;
                for (int i = mq; i <= l - 1; ++i) {
                    float f = s * e[i], b = c * e[i];
                    slartgf(g, f, &c, &s, &r);
                    if (i != mq) e[i - 1] = r;
                    g = d[i] - p;
                    r = (d[i + 1] - g) * s + 2.f * c * b;
                    p = s * r;
                    d[i] = g + p;
                    g = c * r - b;
                    wc[i] = c; ws[i] = s;
                }
                for (int j = 1; j <= l - mq; ++j) {
                    float ct = wc[mq + j - 1], st = ws[mq + j - 1];
                    for (int i = 0; i < 3; ++i) {
                        float t = z[i][mq + j - 1];
                        z[i][mq + j - 1] = ct * t - st * z[i][mq + j - 2];
                        z[i][mq + j - 2] = st * t + ct * z[i][mq + j - 2];
                    }
                }
                d[l] -= p;
                e[l - 1] = g;
            }
        }
    }
    for (int ii = 2; ii <= n; ++ii) {
        int i = ii - 1, k = i;
        float p = d[i];
        for (int j = ii; j <= n; ++j) if (d[j] < p) { k = j; p = d[j]; }
        if (k != i) {
            d[k] = d[i]; d[i] = p;
            for (int r2 = 0; r2 < 3; ++r2) {
                float t = z[r2][i - 1]; z[r2][i - 1] = z[r2][k - 1]; z[r2][k - 1] = t;
            }
        }
    }
}

__device__ void eigh3(const float A[6], float V[3][3]) {
    float a00 = A[0], a10 = A[1], a20 = A[2], a11 = A[3], a21 = A[4], a22 = A[5];
    float tau = 0.f, v2 = 0.f, e0, e1, d1 = a11, d2v = a22;
    float xnorm = fabsf(a20);
    if (xnorm == 0.f) { tau = 0.f; e0 = a10; e1 = a21; }
    else {
        float alpha = a10;
        float beta = -copysignf(slapy2f(alpha, xnorm), alpha);
        tau = (beta - alpha) / beta;
        v2 = a20 * (1.f / (alpha - beta));
        e0 = beta;
        float w0 = tau * a11 + tau * (a21 * v2);
        float w1 = tau * a21 + (tau * v2) * a22;
        float aw = -0.5f * tau * (w0 + w1 * v2);
        w0 += aw; w1 += aw * v2;
        d1  = (a11 - w0) - w0;
        e1  = (a21 - v2 * w0) - w1;
        d2v = (a22 - v2 * w1) - w1 * v2;
    }
    float d[3] = {a00, d1, d2v};
    float e[2] = {e0, e1};
    ssteqr3(d, e, V);
    if (tau != 0.f) {
        for (int j = 0; j < 3; ++j) {
            float s = V[1][j] + v2 * V[2][j];
            V[1][j] -= tau * s;
            V[2][j] -= tau * v2 * s;
        }
    }
}

// ---------------------------------------------------------------------------
__device__ __forceinline__ unsigned long long warp_min64(unsigned long long k) {
    unsigned hi = (unsigned)(k >> 32), lo = (unsigned)k;
    unsigned mhi = __reduce_min_sync(0xffffffffu, hi);
    unsigned lo2 = (hi == mhi) ? lo : 0xffffffffu;
    unsigned mlo = __reduce_min_sync(0xffffffffu, lo2);
    return ((unsigned long long)mhi << 32) | mlo;
}

__device__ __forceinline__ unsigned f2u(float f) {
    int i = __float_as_int(f);
    return (i < 0) ? ~(unsigned)i : ((unsigned)i | 0x80000000u);
}

__global__ void prep_kernel(const float* __restrict__ pos) {
    int p = blockIdx.x * blockDim.x + threadIdx.x;
    if (p < NP) {
        float x = pos[3 * p], y = pos[3 * p + 1], z = pos[3 * p + 2];
        g_posq[p] = make_float4(x, y, z, x * x + y * y + z * z);
    }
}

__global__ void transpose_coef_kernel(const float* __restrict__ coef) {
    int i = blockIdx.x * blockDim.x + threadIdx.x;     // over COUT*NG = 13824
    if (i < COUT * NG) {
        int o = i / NG, j = i - o * NG;
        g_coefT[(j >> 2) * 128 + o * 4 + (j & 3)] = coef[i];
    }
}

// ---------------------------------------------------------------------------
// Kernel 1: exact kNN, 8 queries per block (amortize position reads 8x)
// ---------------------------------------------------------------------------
__global__ __launch_bounds__(256)
void knn_kernel() {
    const int tid = threadIdx.x;
    const int lane = tid & 31;
    const int wid = tid >> 5;
    const int qbase = blockIdx.x * QB;

    __shared__ unsigned long long s_surv[QB][SCAP];
    __shared__ unsigned s_b4[QB][8];
    __shared__ int s_cnt[QB];

    if (tid < QB) s_cnt[tid] = 0;

    // query positions in registers
    float4 pq[QB];
#pragma unroll
    for (int q = 0; q < QB; ++q) pq[q] = g_posq[qbase + q];

    // ---- Pass 1: per-thread min d2 per query over its 16 candidates --------
    float mn[QB];
#pragma unroll
    for (int q = 0; q < QB; ++q) mn[q] = __int_as_float(0x7f800000);

#pragma unroll 4
    for (int j = 0; j < 16; ++j) {
        int cand = tid + (j << 8);
        float4 cq = g_posq[cand];
#pragma unroll
        for (int q = 0; q < QB; ++q) {
            float dot = pq[q].x * cq.x + pq[q].y * cq.y + pq[q].z * cq.z;
            float d2 = (pq[q].w + cq.w) - 2.f * dot;
            mn[q] = fminf(mn[q], d2);
        }
    }

    // ---- Bound per query: max over warps of warp-4th-smallest thread-min ---
    // >=4 distinct candidates per warp have key <= bound -> >=32 total.
#pragma unroll
    for (int q = 0; q < QB; ++q) {
        unsigned h = f2u(mn[q]), w4 = 0;
#pragma unroll
        for (int r = 0; r < 4; ++r) {
            w4 = __reduce_min_sync(0xffffffffu, h);
            if (h == w4) h = 0xffffffffu;
        }
        if (lane == 0) s_b4[q][wid] = w4;
    }
    __syncthreads();

    float Bf[QB];
#pragma unroll
    for (int q = 0; q < QB; ++q) {
        unsigned B = s_b4[q][0];
#pragma unroll
        for (int w = 1; w < 8; ++w) B = max(B, s_b4[q][w]);
        int bi = (B & 0x80000000u) ? (int)(B & 0x7fffffffu) : (int)~B;
        Bf[q] = __int_as_float(bi);
    }

    // ---- Pass 2: recompute (L1 hits), filter d2 <= Bf, gather survivors ----
#pragma unroll 4
    for (int j = 0; j < 16; ++j) {
        int cand = tid + (j << 8);
        float4 cq = g_posq[cand];
#pragma unroll
        for (int q = 0; q < QB; ++q) {
            float dot = pq[q].x * cq.x + pq[q].y * cq.y + pq[q].z * cq.z;
            float d2 = (pq[q].w + cq.w) - 2.f * dot;
            if (d2 <= Bf[q]) {
                unsigned u = f2u(d2);
                int pos = atomicAdd(&s_cnt[q], 1);
                if (pos < SCAP)
                    s_surv[q][pos] = ((unsigned long long)u << 32) | (unsigned)cand;
            }
        }
    }
    __syncthreads();

    // ---- Extraction: warp w extracts top-32 of query w (parallel) ----------
    {
        const int q = wid;
        int S = s_cnt[q] < SCAP ? s_cnt[q] : SCAP;
        for (int r = 0; r < KNN; ++r) {
            unsigned long long m = ~0ULL; int mi = -1;
            for (int i = lane; i < S; i += 32) {
                unsigned long long v = s_surv[q][i];
                if (v < m) { m = v; mi = i; }
            }
            unsigned long long w = warp_min64(m);
            if (m == w && mi >= 0) s_surv[q][mi] = ~0ULL;   // unique owner
            if (lane == 0) g_nbr[(qbase + q) * KNN + r] = (int)(w & 0xffffffffu);
        }
    }
}

// ---------------------------------------------------------------------------
// Kernel 2: per-point conv, one warp per point, 4 warps/block (grid 1024)
// ---------------------------------------------------------------------------
__global__ __launch_bounds__(128)
void conv_kernel(const float* __restrict__ chan,
                 float* __restrict__ centers_out,
                 float* __restrict__ out) {
    const int tid = threadIdx.x;
    const int lane = tid & 31;
    const int wid = tid >> 5;
    const int p = blockIdx.x * 4 + wid;

    __shared__ float s_basis[4][32][28];
    __shared__ float s_G[4][448];
    __shared__ float s_feat[4][32][16];

    const int nb = g_nbr[p * KNN + lane];
    const float4 q = g_posq[nb];

    // preload this lane's neighbor features (coalesced float4, no shfl dep)
    {
        const float4* fr = (const float4*)(chan + nb * CIN);
        float4 f0 = fr[0], f1 = fr[1], f2 = fr[2], f3 = fr[3];
        float4* sf = (float4*)&s_feat[wid][lane][0];
        sf[0] = f0; sf[1] = f1; sf[2] = f2; sf[3] = f3;
    }

    // center (butterfly sum -> identical value on all lanes), exact /32
    float cx = q.x, cy = q.y, cz = q.z;
#pragma unroll
    for (int off = 16; off; off >>= 1) {
        cx += __shfl_xor_sync(0xffffffffu, cx, off);
        cy += __shfl_xor_sync(0xffffffffu, cy, off);
        cz += __shfl_xor_sync(0xffffffffu, cz, off);
    }
    cx *= 0.03125f; cy *= 0.03125f; cz *= 0.03125f;
    if (lane == 0) {
        centers_out[3 * p]     = cx;
        centers_out[3 * p + 1] = cy;
        centers_out[3 * p + 2] = cz;
    }

    const float lx = q.x - cx, ly = q.y - cy, lz = q.z - cz;

    // covariance (6 butterfly reductions), exact /32
    float c00 = lx * lx, c01 = lx * ly, c02 = lx * lz;
    float c11 = ly * ly, c12 = ly * lz, c22 = lz * lz;
#pragma unroll
    for (int off = 16; off; off >>= 1) {
        c00 += __shfl_xor_sync(0xffffffffu, c00, off);
        c01 += __shfl_xor_sync(0xffffffffu, c01, off);
        c02 += __shfl_xor_sync(0xffffffffu, c02, off);
        c11 += __shfl_xor_sync(0xffffffffu, c11, off);
        c12 += __shfl_xor_sync(0xffffffffu, c12, off);
        c22 += __shfl_xor_sync(0xffffffffu, c22, off);
    }
    c00 *= 0.03125f; c01 *= 0.03125f; c02 *= 0.03125f;
    c11 *= 0.03125f; c12 *= 0.03125f; c22 *= 0.03125f;

    // eigh on lane 0, broadcast 9 entries
    float v00, v01, v02, v10, v11, v12, v20, v21, v22;
    if (lane == 0) {
        float A[6] = {c00, c01, c02, c11, c12, c22};
        float V[3][3];
        eigh3(A, V);
        v00 = V[0][0]; v01 = V[0][1]; v02 = V[0][2];
        v10 = V[1][0]; v11 = V[1][1]; v12 = V[1][2];
        v20 = V[2][0]; v21 = V[2][1]; v22 = V[2][2];
    }
    v00 = __shfl_sync(0xffffffffu, v00, 0); v01 = __shfl_sync(0xffffffffu, v01, 0);
    v02 = __shfl_sync(0xffffffffu, v02, 0); v10 = __shfl_sync(0xffffffffu, v10, 0);
    v11 = __shfl_sync(0xffffffffu, v11, 0); v12 = __shfl_sync(0xffffffffu, v12, 0);
    v20 = __shfl_sync(0xffffffffu, v20, 0); v21 = __shfl_sync(0xffffffffu, v21, 0);
    v22 = __shfl_sync(0xffffffffu, v22, 0);

    // rotate into PCA frame, spherical coords, 27 basis values
    {
        float x = lx * v00 + ly * v10 + lz * v20;
        float y = lx * v01 + ly * v11 + lz * v21;
        float z = lx * v02 + ly * v12 + lz * v22;
        float r = sqrtf(x * x + y * y + z * z);
        float ct = z / (r + 1e-8f);
        ct = fminf(fmaxf(ct, -1.f + 1e-6f), 1.f - 1e-6f);
        float theta = acosf(ct);
        float phi = atan2f(y, x);
        float rb[3] = {1.f, r, r * r};
        float tb[3] = {1.f, cosf(theta), cosf(2.f * theta)};
        float pb[3] = {1.f, cosf(phi), cosf(2.f * phi)};
#pragma unroll
        for (int n = 0; n < 3; ++n)
#pragma unroll
            for (int l = 0; l < 3; ++l)
#pragma unroll
                for (int m = 0; m < 3; ++m)
                    s_basis[wid][lane][n * 9 + l * 3 + m] = (rb[n] * tb[l]) * pb[m];
        s_basis[wid][lane][27] = 0.f;    // pad (read by half=1 float4 path)
    }
    __syncwarp();

    // phase 4: G[c*27+nlm] = sum_k basis[k][nlm]*feat[k][c]
    // lane -> (c = lane>>1, half = lane&1): half0 nlm 0..15, half1 16..27(pad)
    {
        const int c = lane >> 1;
        const int half = lane & 1;
        float acc[16];
#pragma unroll
        for (int i = 0; i < 16; ++i) acc[i] = 0.f;

#pragma unroll 8
        for (int k = 0; k < KNN; ++k) {
            float fv = s_feat[wid][k][c];
            const float* row = &s_basis[wid][k][0];
            if (half == 0) {
                float4 b0 = *(const float4*)(row);
                float4 b1 = *(const float4*)(row + 4);
                float4 b2 = *(const float4*)(row + 8);
                float4 b3 = *(const float4*)(row + 12);
                acc[0]  += b0.x * fv; acc[1]  += b0.y * fv; acc[2]  += b0.z * fv; acc[3]  += b0.w * fv;
                acc[4]  += b1.x * fv; acc[5]  += b1.y * fv; acc[6]  += b1.z * fv; acc[7]  += b1.w * fv;
                acc[8]  += b2.x * fv; acc[9]  += b2.y * fv; acc[10] += b2.z * fv; acc[11] += b2.w * fv;
                acc[12] += b3.x * fv; acc[13] += b3.y * fv; acc[14] += b3.z * fv; acc[15] += b3.w * fv;
            } else {
                float4 b0 = *(const float4*)(row + 16);
                float4 b1 = *(const float4*)(row + 20);
                float4 b2 = *(const float4*)(row + 24);
                acc[0]  += b0.x * fv; acc[1]  += b0.y * fv; acc[2]  += b0.z * fv; acc[3]  += b0.w * fv;
                acc[4]  += b1.x * fv; acc[5]  += b1.y * fv; acc[6]  += b1.z * fv; acc[7]  += b1.w * fv;
                acc[8]  += b2.x * fv; acc[9]  += b2.y * fv; acc[10] += b2.z * fv;
            }
        }
        if (half == 0) {
#pragma unroll
            for (int i = 0; i < 16; ++i) s_G[wid][c * 27 + i] = acc[i];
        } else {
#pragma unroll
            for (int i = 0; i < 11; ++i) s_G[wid][c * 27 + 16 + i] = acc[i];
        }
    }
    __syncwarp();

    // phase 5: out[o=lane] = sum_j coefT[j][o] * G[j], coalesced float4 loads
    {
        float a0 = 0.f, a1 = 0.f, a2 = 0.f, a3 = 0.f;
        const float* gT = g_coefT + lane * 4;
        const float* gw = &s_G[wid][0];
#pragma unroll 4
        for (int t = 0; t < 108; ++t) {
            float4 cf = *(const float4*)(gT + t * 128);
            float4 gv = *(const float4*)(gw + t * 4);
            a0 += cf.x * gv.x;
            a1 += cf.y * gv.y;
            a2 += cf.z * gv.z;
            a3 += cf.w * gv.w;
        }
        out[p * COUT + lane] = (a0 + a1) + (a2 + a3);
    }
}

extern "C" void kernel_launch(void* const* d_in, const int* in_sizes, int n_in,
                              void* d_out, int out_size) {
    const float* pos  = (const float*)d_in[0];
    const float* chan = (const float*)d_in[1];
    const float* coef = (const float*)d_in[3];

    float* d_outf = (float*)d_out;
    float* centers_ptr;
    float* out_ptr;
    if (out_size == NP * 3 + NP * COUT) {
        centers_ptr = d_outf;
        out_ptr     = d_outf + NP * 3;
    } else if (out_size == NP * COUT) {
        cudaGetSymbolAddress((void**)&centers_ptr, g_cscratch);
        out_ptr = d_outf;
    } else {
        centers_ptr = d_outf;
        cudaGetSymbolAddress((void**)&out_ptr, g_oscratch);
    }

    prep_kernel<<<32, 128>>>(pos);
    transpose_coef_kernel<<<54, 256>>>(coef);
    knn_kernel<<<NP / QB, 256>>>();
    conv_kernel<<<NP / 4, 128>>>(chan, centers_ptr, out_ptr);
}